// round 1
// baseline (speedup 1.0000x reference)
#include <cuda_runtime.h>
#include <cuda_bf16.h>
#include <cstdint>

// Problem constants (from reference):
//   NUM_BLOCKS=1024, BLOCK_SIZE=128, NUM_TOKENS=8192, NUM_KV_HEADS=8, HEAD_SIZE=128
// Row per token = 8*128 = 1024 fp32 = 4096 B = 256 float4.

static constexpr long long INPUT_ELEMS = 8192LL * 8 * 128;  // 8,388,608
static constexpr int NUM_TOKENS = 8192;
static constexpr int ROW_F4 = 256;  // 1024 floats / 4

__global__ void kv_scatter_kernel(const float4* __restrict__ in,
                                  const int* __restrict__ block_indices,
                                  const int* __restrict__ block_offset,
                                  float4* __restrict__ out) {
    const int t = blockIdx.x;               // token id, 0..8191
    // flat slot = block_indices[t] * BLOCK_SIZE + block_offset[t]
    const long long slot = (long long)__ldg(&block_indices[t]) * 128
                         + (long long)__ldg(&block_offset[t]);
    const int lane = threadIdx.x;           // 0..255, one float4 each
    out[slot * ROW_F4 + lane] = in[(long long)t * ROW_F4 + lane];
}

extern "C" void kernel_launch(void* const* d_in, const int* in_sizes, int n_in,
                              void* d_out, int out_size) {
    const float* input = nullptr;
    const float* cache = nullptr;
    const int* block_indices = nullptr;
    const int* block_offset = nullptr;

    // Identify inputs by element count (robust to scalar args being present or not).
    for (int i = 0; i < n_in; i++) {
        const long long sz = (long long)in_sizes[i];
        if (sz == INPUT_ELEMS && input == nullptr) {
            input = (const float*)d_in[i];
        } else if (sz == (long long)out_size && cache == nullptr) {
            cache = (const float*)d_in[i];
        } else if (sz == NUM_TOKENS) {
            if (block_indices == nullptr) block_indices = (const int*)d_in[i];
            else if (block_offset == nullptr) block_offset = (const int*)d_in[i];
        }
    }

    float* out = (float*)d_out;

    // 1) Bulk copy cache -> out (graph-capturable async D2D on default stream).
    cudaMemcpyAsync(out, cache, (size_t)out_size * sizeof(float),
                    cudaMemcpyDeviceToDevice, 0);

    // 2) Scatter the 8192 token rows (4 KB each) over the copy, same stream => ordered.
    kv_scatter_kernel<<<NUM_TOKENS, ROW_F4, 0, 0>>>(
        (const float4*)input, block_indices, block_offset, (float4*)out);
}

// round 2
// speedup vs baseline: 2.2042x; 2.2042x over previous
#include <cuda_runtime.h>
#include <cuda_bf16.h>
#include <cstdint>

// Problem constants (from reference):
//   NUM_BLOCKS=1024, BLOCK_SIZE=128, NUM_TOKENS=8192, NUM_KV_HEADS=8, HEAD_SIZE=128
// Row per (block,offset) slot = 8*128 = 1024 fp32 = 4096 B = 256 float4.

static constexpr long long INPUT_ELEMS = 8192LL * 8 * 128;  // 8,388,608
static constexpr int NUM_TOKENS = 8192;
static constexpr int NUM_ROWS = 1024 * 128;   // 131072 slot rows in the cache
static constexpr int ROW_F4 = 256;            // float4 per row
static constexpr int ROWS_PER_CTA = 4;

// Inverse slot map: map[row] = token_id + 1, or 0 if no token scatters to row.
// 131072 * 4 B = 512 KB device scratch (allowed: __device__ global).
__device__ int g_slot_map[NUM_ROWS];

__global__ void fill_map_kernel(const int* __restrict__ block_indices,
                                const int* __restrict__ block_offset) {
    const int t = blockIdx.x * blockDim.x + threadIdx.x;
    if (t < NUM_TOKENS) {
        const int slot = block_indices[t] * 128 + block_offset[t];
        g_slot_map[slot] = t + 1;
    }
}

// One pass over the whole output. Each CTA: 4 rows x 4 KB = 16 KB.
// All 4 loads issued before any store for MLP.
__global__ void __launch_bounds__(256) fused_scatter_copy_kernel(
    const float4* __restrict__ in,
    const float4* __restrict__ cache,
    float4* __restrict__ out) {
    const int row0 = blockIdx.x * ROWS_PER_CTA;
    const int lane = threadIdx.x;  // 0..255

    const float4* src[ROWS_PER_CTA];
    float4 v[ROWS_PER_CTA];

#pragma unroll
    for (int r = 0; r < ROWS_PER_CTA; r++) {
        const int row = row0 + r;
        const int t = g_slot_map[row];  // broadcast load (same addr across CTA)
        src[r] = (t != 0) ? (in + (long long)(t - 1) * ROW_F4)
                          : (cache + (long long)row * ROW_F4);
    }
#pragma unroll
    for (int r = 0; r < ROWS_PER_CTA; r++) v[r] = src[r][lane];
#pragma unroll
    for (int r = 0; r < ROWS_PER_CTA; r++)
        out[(long long)(row0 + r) * ROW_F4 + lane] = v[r];
}

extern "C" void kernel_launch(void* const* d_in, const int* in_sizes, int n_in,
                              void* d_out, int out_size) {
    const float* input = nullptr;
    const float* cache = nullptr;
    const int* block_indices = nullptr;
    const int* block_offset = nullptr;

    // Identify inputs by element count (robust to scalar args being present or not).
    for (int i = 0; i < n_in; i++) {
        const long long sz = (long long)in_sizes[i];
        if (sz == INPUT_ELEMS && input == nullptr) {
            input = (const float*)d_in[i];
        } else if (sz == (long long)out_size && cache == nullptr) {
            cache = (const float*)d_in[i];
        } else if (sz == NUM_TOKENS) {
            if (block_indices == nullptr) block_indices = (const int*)d_in[i];
            else if (block_offset == nullptr) block_offset = (const int*)d_in[i];
        }
    }

    float* out = (float*)d_out;

    // 1) Reset inverse map (graph-capturable, no alloc).
    void* map_ptr = nullptr;
    cudaGetSymbolAddress(&map_ptr, g_slot_map);
    cudaMemsetAsync(map_ptr, 0, NUM_ROWS * sizeof(int), 0);

    // 2) Build inverse map: map[slot] = token + 1.
    fill_map_kernel<<<(NUM_TOKENS + 255) / 256, 256, 0, 0>>>(block_indices, block_offset);

    // 3) Single fused pass producing the full output.
    fused_scatter_copy_kernel<<<NUM_ROWS / ROWS_PER_CTA, 256, 0, 0>>>(
        (const float4*)input, (const float4*)cache, (float4*)out);
}

// round 3
// speedup vs baseline: 2.2334x; 1.0132x over previous
#include <cuda_runtime.h>
#include <cuda_bf16.h>
#include <cstdint>

// Problem constants (from reference):
//   NUM_BLOCKS=1024, BLOCK_SIZE=128, NUM_TOKENS=8192, NUM_KV_HEADS=8, HEAD_SIZE=128
// Row per (block,offset) slot = 8*128 = 1024 fp32 = 4096 B = 256 float4.

static constexpr long long INPUT_ELEMS = 8192LL * 8 * 128;  // 8,388,608
static constexpr int NUM_TOKENS = 8192;
static constexpr int NUM_ROWS = 1024 * 128;   // 131072 slot rows in the cache
static constexpr int ROW_F4 = 256;            // float4 per row
static constexpr int ROWS_PER_CTA = 4;

// Inverse slot map: map[row] = token_id + 1, or 0 if no token scatters to row.
// Statically zero-initialized; the main pass clears the entries it consumed,
// so every graph replay starts from an all-zero map (no memset node needed).
__device__ int g_slot_map[NUM_ROWS];

__global__ void fill_map_kernel(const int* __restrict__ block_indices,
                                const int* __restrict__ block_offset) {
    const int t = blockIdx.x * blockDim.x + threadIdx.x;
    if (t < NUM_TOKENS) {
        const int slot = block_indices[t] * 128 + block_offset[t];
        g_slot_map[slot] = t + 1;
    }
}

// One pass over the whole output. Each CTA: 4 rows x 4 KB = 16 KB.
// All 4 loads issued before any store for MLP. Streaming hints: every byte
// is touched exactly once, so bypass/evict-first in L2.
__global__ void __launch_bounds__(256) fused_scatter_copy_kernel(
    const float4* __restrict__ in,
    const float4* __restrict__ cache,
    float4* __restrict__ out) {
    const int row0 = blockIdx.x * ROWS_PER_CTA;
    const int lane = threadIdx.x;  // 0..255

    const float4* src[ROWS_PER_CTA];
    int tok[ROWS_PER_CTA];
    float4 v[ROWS_PER_CTA];

#pragma unroll
    for (int r = 0; r < ROWS_PER_CTA; r++) {
        const int row = row0 + r;
        tok[r] = g_slot_map[row];  // broadcast load (same addr across CTA)
        src[r] = (tok[r] != 0) ? (in + (long long)(tok[r] - 1) * ROW_F4)
                               : (cache + (long long)row * ROW_F4);
    }
#pragma unroll
    for (int r = 0; r < ROWS_PER_CTA; r++) v[r] = __ldcs(&src[r][lane]);
#pragma unroll
    for (int r = 0; r < ROWS_PER_CTA; r++)
        __stcs(&out[(long long)(row0 + r) * ROW_F4 + lane], v[r]);

    // Self-clean the map for the next graph replay (32 KB total across grid).
    if (lane == 0) {
#pragma unroll
        for (int r = 0; r < ROWS_PER_CTA; r++)
            if (tok[r] != 0) g_slot_map[row0 + r] = 0;
    }
}

extern "C" void kernel_launch(void* const* d_in, const int* in_sizes, int n_in,
                              void* d_out, int out_size) {
    const float* input = nullptr;
    const float* cache = nullptr;
    const int* block_indices = nullptr;
    const int* block_offset = nullptr;

    // Identify inputs by element count (robust to scalar args being present or not).
    for (int i = 0; i < n_in; i++) {
        const long long sz = (long long)in_sizes[i];
        if (sz == INPUT_ELEMS && input == nullptr) {
            input = (const float*)d_in[i];
        } else if (sz == (long long)out_size && cache == nullptr) {
            cache = (const float*)d_in[i];
        } else if (sz == NUM_TOKENS) {
            if (block_indices == nullptr) block_indices = (const int*)d_in[i];
            else if (block_offset == nullptr) block_offset = (const int*)d_in[i];
        }
    }

    float* out = (float*)d_out;

    // 1) Build inverse map: map[slot] = token + 1 (map arrives all-zero).
    fill_map_kernel<<<(NUM_TOKENS + 255) / 256, 256, 0, 0>>>(block_indices, block_offset);

    // 2) Single fused pass producing the full output; clears the map as it goes.
    fused_scatter_copy_kernel<<<NUM_ROWS / ROWS_PER_CTA, 256, 0, 0>>>(
        (const float4*)input, (const float4*)cache, (float4*)out);
}